// round 1
// baseline (speedup 1.0000x reference)
#include <cuda_runtime.h>
#include <cstdint>
#include <math.h>

#define BB   4
#define NNQ  2048
#define DDIM 512
#define HHH  8
#define ROWS (BB * NNQ)        // 8192
#define MMW  2048              // 2*H*DL + 2*H*DA

// Scratch (allocation-free: __device__ globals)
__device__ float g_xn[ROWS * DDIM];            // 16 MB  normed x
__device__ float g_mm[(size_t)ROWS * MMW];     // 64 MB  silu(xn @ uvqk): [u|v|q|k]
__device__ float g_attn[ROWS * DDIM];          // 16 MB  attention output
__device__ float g_oin[ROWS * DDIM];           // 16 MB  u * LN(attn)

__device__ __forceinline__ float silu_f(float v) {
    return v / (1.f + __expf(-v));
}

// ---------------------------------------------------------------------------
// LayerNorm over last dim (512). GATE: also multiply by u (stride MMW).
// ---------------------------------------------------------------------------
template<bool GATE>
__global__ __launch_bounds__(256) void ln_kernel(const float* __restrict__ xin,
                                                 const float* __restrict__ u,
                                                 float* __restrict__ outp)
{
    const int row = blockIdx.x;
    const int t   = threadIdx.x;
    const float* xr = xin + (size_t)row * DDIM;
    float v0 = xr[t];
    float v1 = xr[t + 256];
    float s  = v0 + v1;
    float ss = v0 * v0 + v1 * v1;
    #pragma unroll
    for (int o = 16; o > 0; o >>= 1) {
        s  += __shfl_xor_sync(0xffffffffu, s, o);
        ss += __shfl_xor_sync(0xffffffffu, ss, o);
    }
    __shared__ float red[16];
    __shared__ float stats[2];
    const int w = t >> 5;
    if ((t & 31) == 0) { red[w] = s; red[8 + w] = ss; }
    __syncthreads();
    if (t == 0) {
        float a = 0.f, b2 = 0.f;
        #pragma unroll
        for (int i = 0; i < 8; i++) { a += red[i]; b2 += red[8 + i]; }
        float mu  = a * (1.f / DDIM);
        float var = b2 * (1.f / DDIM) - mu * mu;
        stats[0] = mu;
        stats[1] = rsqrtf(var + 1e-6f);
    }
    __syncthreads();
    const float mu = stats[0], r = stats[1];
    float o0 = (v0 - mu) * r;
    float o1 = (v1 - mu) * r;
    if (GATE) {
        o0 *= u[(size_t)row * MMW + t];
        o1 *= u[(size_t)row * MMW + t + 256];
    }
    outp[(size_t)row * DDIM + t]       = o0;
    outp[(size_t)row * DDIM + t + 256] = o1;
}

// ---------------------------------------------------------------------------
// SGEMM 128x128x16, 256 threads, 8x8 microtiles.
// EPI==0: C = silu(A @ B),      B row-major [K x Nn]
// EPI==1: C = A @ B^T + bias + res,  B row-major [Nn x K]
// ---------------------------------------------------------------------------
template<int EPI>
__global__ __launch_bounds__(256) void sgemm_kernel(
    const float* __restrict__ A, const float* __restrict__ Bm,
    const float* __restrict__ bias, const float* __restrict__ res,
    float* __restrict__ C, int M, int Nn, int K)
{
    __shared__ float As[16 * 132];
    __shared__ float Bs[16 * 132];
    const int tid = threadIdx.x;
    const int n0 = blockIdx.x * 128;
    const int m0 = blockIdx.y * 128;
    const int ty = tid >> 4, tx = tid & 15;
    float acc[8][8] = {};

    for (int k0 = 0; k0 < K; k0 += 16) {
        // A tile -> As[k][m] (transposed)
        #pragma unroll
        for (int ii = 0; ii < 2; ii++) {
            int f = tid + ii * 256;
            int r = f >> 2, cg = (f & 3) << 2;
            float4 a4 = *(const float4*)(A + (size_t)(m0 + r) * K + k0 + cg);
            As[(cg + 0) * 132 + r] = a4.x;
            As[(cg + 1) * 132 + r] = a4.y;
            As[(cg + 2) * 132 + r] = a4.z;
            As[(cg + 3) * 132 + r] = a4.w;
        }
        if (EPI == 0) {
            #pragma unroll
            for (int ii = 0; ii < 2; ii++) {
                int f = tid + ii * 256;
                int r = f >> 5, c = (f & 31) << 2;
                float4 b4 = *(const float4*)(Bm + (size_t)(k0 + r) * Nn + n0 + c);
                *(float4*)&Bs[r * 132 + c] = b4;
            }
        } else {
            // B transposed: element (k, n) = Bm[n*K + k]
            #pragma unroll
            for (int ii = 0; ii < 2; ii++) {
                int f = tid + ii * 256;
                int nn2 = f >> 2, kg = (f & 3) << 2;
                float4 b4 = *(const float4*)(Bm + (size_t)(n0 + nn2) * K + k0 + kg);
                Bs[(kg + 0) * 132 + nn2] = b4.x;
                Bs[(kg + 1) * 132 + nn2] = b4.y;
                Bs[(kg + 2) * 132 + nn2] = b4.z;
                Bs[(kg + 3) * 132 + nn2] = b4.w;
            }
        }
        __syncthreads();
        #pragma unroll
        for (int kk = 0; kk < 16; kk++) {
            float av[8], bv[8];
            *(float4*)&av[0] = *(float4*)&As[kk * 132 + ty * 8];
            *(float4*)&av[4] = *(float4*)&As[kk * 132 + ty * 8 + 4];
            *(float4*)&bv[0] = *(float4*)&Bs[kk * 132 + tx * 8];
            *(float4*)&bv[4] = *(float4*)&Bs[kk * 132 + tx * 8 + 4];
            #pragma unroll
            for (int i = 0; i < 8; i++)
                #pragma unroll
                for (int j = 0; j < 8; j++)
                    acc[i][j] += av[i] * bv[j];
        }
        __syncthreads();
    }

    #pragma unroll
    for (int i = 0; i < 8; i++) {
        int gm = m0 + ty * 8 + i;
        #pragma unroll
        for (int j = 0; j < 8; j += 4) {
            int gn = n0 + tx * 8 + j;
            float4 c4;
            c4.x = acc[i][j]; c4.y = acc[i][j + 1]; c4.z = acc[i][j + 2]; c4.w = acc[i][j + 3];
            if (EPI == 0) {
                c4.x = silu_f(c4.x); c4.y = silu_f(c4.y);
                c4.z = silu_f(c4.z); c4.w = silu_f(c4.w);
            } else {
                float4 r4 = *(const float4*)(res + (size_t)gm * Nn + gn);
                float4 b4 = *(const float4*)(bias + gn);
                c4.x += b4.x + r4.x; c4.y += b4.y + r4.y;
                c4.z += b4.z + r4.z; c4.w += b4.w + r4.w;
            }
            *(float4*)&C[(size_t)gm * Nn + gn] = c4;
        }
    }
}

// ---------------------------------------------------------------------------
// Fused causal silu-attention (no softmax):
//   O[n,:] = sum_{m<=n} (silu(q_n . k_m) / N) * v_m      per (b, h)
// Tile: 128 n-rows per block, loop over 128-wide m-tiles up to the diagonal.
// ---------------------------------------------------------------------------
#define QS_STRIDE 132
#define VS_STRIDE 68
#define ATTN_SMEM_FLOATS (64 * 132 + 64 * 132 + 128 * 68 + 128 * 132)  // 42496

__global__ __launch_bounds__(256) void attn_kernel(const float* __restrict__ mm,
                                                   float* __restrict__ attn_out)
{
    extern __shared__ float smbuf[];
    float* Qs = smbuf;                 // [64 d][132]  (d-major / transposed)
    float* Ks = Qs + 64 * QS_STRIDE;   // [64 d][132]
    float* Vs = Ks + 64 * QS_STRIDE;   // [128 j][68]
    float* Ss = Vs + 128 * VS_STRIDE;  // [128 j][132] (S transposed: Ss[j][i])

    const int tid = threadIdx.x;
    const int nt  = (int)gridDim.x - 1 - (int)blockIdx.x;  // heavy tiles dispatched first
    const int bh  = blockIdx.y;
    const int b   = bh >> 3, h = bh & 7;
    const size_t rowbase = (size_t)b * NNQ;
    const float* qbase = mm + rowbase * MMW + 1024 + h * 64;
    const float* kbase = mm + rowbase * MMW + 1536 + h * 64;
    const float* vbase = mm + rowbase * MMW + 512  + h * 64;
    const int n0 = nt * 128;

    // Load Q tile (transposed to d-major)
    #pragma unroll
    for (int ii = 0; ii < 8; ii++) {
        int f = tid + ii * 256;            // 0..2047
        int r = f >> 4, cg = (f & 15) << 2;
        float4 q4 = *(const float4*)(qbase + (size_t)(n0 + r) * MMW + cg);
        Qs[(cg + 0) * QS_STRIDE + r] = q4.x;
        Qs[(cg + 1) * QS_STRIDE + r] = q4.y;
        Qs[(cg + 2) * QS_STRIDE + r] = q4.z;
        Qs[(cg + 3) * QS_STRIDE + r] = q4.w;
    }

    const int i0  = (tid >> 4) * 8;
    const int j0  = (tid & 15) * 8;
    const int dl0 = (tid & 15) * 4;
    float o_acc[8][4] = {};
    const float inv_n = 1.0f / (float)NNQ;

    for (int mt = 0; mt <= nt; mt++) {
        const int m0 = mt * 128;
        __syncthreads();   // prev AV done (and Q visible on first iter)
        #pragma unroll
        for (int ii = 0; ii < 8; ii++) {
            int f = tid + ii * 256;
            int r = f >> 4, cg = (f & 15) << 2;
            float4 k4 = *(const float4*)(kbase + (size_t)(m0 + r) * MMW + cg);
            Ks[(cg + 0) * QS_STRIDE + r] = k4.x;
            Ks[(cg + 1) * QS_STRIDE + r] = k4.y;
            Ks[(cg + 2) * QS_STRIDE + r] = k4.z;
            Ks[(cg + 3) * QS_STRIDE + r] = k4.w;
            float4 v4 = *(const float4*)(vbase + (size_t)(m0 + r) * MMW + cg);
            *(float4*)&Vs[r * VS_STRIDE + cg] = v4;
        }
        __syncthreads();

        // S = Q K^T (each thread 8x8)
        float s[8][8] = {};
        #pragma unroll 8
        for (int d = 0; d < 64; d++) {
            float av[8], bv[8];
            *(float4*)&av[0] = *(float4*)&Qs[d * QS_STRIDE + i0];
            *(float4*)&av[4] = *(float4*)&Qs[d * QS_STRIDE + i0 + 4];
            *(float4*)&bv[0] = *(float4*)&Ks[d * QS_STRIDE + j0];
            *(float4*)&bv[4] = *(float4*)&Ks[d * QS_STRIDE + j0 + 4];
            #pragma unroll
            for (int i = 0; i < 8; i++)
                #pragma unroll
                for (int j = 0; j < 8; j++)
                    s[i][j] += av[i] * bv[j];
        }
        // silu / N + causal mask, store transposed into Ss[j][i]
        #pragma unroll
        for (int i = 0; i < 8; i++) {
            int gi = n0 + i0 + i;
            #pragma unroll
            for (int j = 0; j < 8; j++) {
                int gj = m0 + j0 + j;
                float v = s[i][j];
                v = (gj <= gi) ? (v / (1.f + __expf(-v))) * inv_n : 0.f;
                Ss[(j0 + j) * QS_STRIDE + i0 + i] = v;
            }
        }
        __syncthreads();

        // O += S @ V (each thread 8 rows x 4 dl-cols)
        #pragma unroll 4
        for (int j = 0; j < 128; j++) {
            float4 vv = *(float4*)&Vs[j * VS_STRIDE + dl0];
            float si[8];
            *(float4*)&si[0] = *(float4*)&Ss[j * QS_STRIDE + i0];
            *(float4*)&si[4] = *(float4*)&Ss[j * QS_STRIDE + i0 + 4];
            #pragma unroll
            for (int i = 0; i < 8; i++) {
                o_acc[i][0] += si[i] * vv.x;
                o_acc[i][1] += si[i] * vv.y;
                o_acc[i][2] += si[i] * vv.z;
                o_acc[i][3] += si[i] * vv.w;
            }
        }
    }

    #pragma unroll
    for (int i = 0; i < 8; i++) {
        size_t row = rowbase + n0 + i0 + i;
        *(float4*)&attn_out[row * DDIM + h * 64 + dl0] = *(float4*)&o_acc[i][0];
    }
}

// ---------------------------------------------------------------------------
extern "C" void kernel_launch(void* const* d_in, const int* in_sizes, int n_in,
                              void* d_out, int out_size)
{
    const float* x = nullptr; const float* uvqk = nullptr;
    const float* o_w = nullptr; const float* o_b = nullptr;
    for (int i = 0; i < n_in; i++) {
        int sz = in_sizes[i];
        if      (sz == ROWS * DDIM)  x    = (const float*)d_in[i];
        else if (sz == DDIM * MMW)   uvqk = (const float*)d_in[i];
        else if (sz == DDIM * DDIM)  o_w  = (const float*)d_in[i];
        else if (sz == DDIM)         o_b  = (const float*)d_in[i];
        // attention_mask (B*1*N*N) is the fixed causal tril; handled analytically
    }
    float* outp = (float*)d_out;

    float *p_xn, *p_mm, *p_attn, *p_oin;
    cudaGetSymbolAddress((void**)&p_xn,   g_xn);
    cudaGetSymbolAddress((void**)&p_mm,   g_mm);
    cudaGetSymbolAddress((void**)&p_attn, g_attn);
    cudaGetSymbolAddress((void**)&p_oin,  g_oin);

    // 1) xn = LN(x)
    ln_kernel<false><<<ROWS, 256>>>(x, nullptr, p_xn);
    // 2) mm = silu(xn @ uvqk)  [8192 x 2048]
    sgemm_kernel<0><<<dim3(MMW / 128, ROWS / 128), 256>>>(
        p_xn, uvqk, nullptr, nullptr, p_mm, ROWS, MMW, DDIM);
    // 3) attn = causal silu-attention
    cudaFuncSetAttribute(attn_kernel, cudaFuncAttributeMaxDynamicSharedMemorySize,
                         ATTN_SMEM_FLOATS * 4);
    attn_kernel<<<dim3(NNQ / 128, BB * HHH), 256, ATTN_SMEM_FLOATS * 4>>>(p_mm, p_attn);
    // 4) oin = u * LN(attn)
    ln_kernel<true><<<ROWS, 256>>>(p_attn, p_mm, p_oin);
    // 5) out = oin @ o_w^T + o_b + x
    sgemm_kernel<1><<<dim3(DDIM / 128, ROWS / 128), 256>>>(
        p_oin, o_w, o_b, x, outp, ROWS, DDIM, DDIM);
}

// round 3
// speedup vs baseline: 1.4245x; 1.4245x over previous
#include <cuda_runtime.h>
#include <cstdint>
#include <math.h>

#define BB   4
#define NNQ  2048
#define DDIM 512
#define HHH  8
#define ROWS (BB * NNQ)        // 8192
#define MMW  2048              // 2*H*DL + 2*H*DA

// Scratch (allocation-free: __device__ globals)
__device__ float g_xn[ROWS * DDIM];            // normed x
__device__ float g_mm[(size_t)ROWS * MMW];     // silu(xn @ uvqk): [u|v|q|k]
__device__ float g_attn[ROWS * DDIM];          // attention output
__device__ float g_oin[ROWS * DDIM];           // u * LN(attn)

__device__ __forceinline__ float silu_f(float v) {
    return v / (1.f + __expf(-v));
}
__device__ __forceinline__ uint32_t f2tf(float x) {
    uint32_t r; asm("cvt.rna.tf32.f32 %0, %1;" : "=r"(r) : "f"(x)); return r;
}
__device__ __forceinline__ void mma8(float c[4], const uint32_t a[4], const uint32_t b[2]) {
    asm volatile(
        "mma.sync.aligned.m16n8k8.row.col.f32.tf32.tf32.f32 "
        "{%0,%1,%2,%3}, {%4,%5,%6,%7}, {%8,%9}, {%0,%1,%2,%3};\n"
        : "+f"(c[0]), "+f"(c[1]), "+f"(c[2]), "+f"(c[3])
        : "r"(a[0]), "r"(a[1]), "r"(a[2]), "r"(a[3]), "r"(b[0]), "r"(b[1]));
}

// ---------------------------------------------------------------------------
// LayerNorm over last dim (512). GATE: also multiply by u (stride MMW).
// ---------------------------------------------------------------------------
template<bool GATE>
__global__ __launch_bounds__(256) void ln_kernel(const float* __restrict__ xin,
                                                 const float* __restrict__ u,
                                                 float* __restrict__ outp)
{
    const int row = blockIdx.x;
    const int t   = threadIdx.x;
    const float* xr = xin + (size_t)row * DDIM;
    float v0 = xr[t];
    float v1 = xr[t + 256];
    float s  = v0 + v1;
    float ss = v0 * v0 + v1 * v1;
    #pragma unroll
    for (int o = 16; o > 0; o >>= 1) {
        s  += __shfl_xor_sync(0xffffffffu, s, o);
        ss += __shfl_xor_sync(0xffffffffu, ss, o);
    }
    __shared__ float red[16];
    __shared__ float stats[2];
    const int w = t >> 5;
    if ((t & 31) == 0) { red[w] = s; red[8 + w] = ss; }
    __syncthreads();
    if (t == 0) {
        float a = 0.f, b2 = 0.f;
        #pragma unroll
        for (int i = 0; i < 8; i++) { a += red[i]; b2 += red[8 + i]; }
        float mu  = a * (1.f / DDIM);
        float var = b2 * (1.f / DDIM) - mu * mu;
        stats[0] = mu;
        stats[1] = rsqrtf(var + 1e-6f);
    }
    __syncthreads();
    const float mu = stats[0], r = stats[1];
    float o0 = (v0 - mu) * r;
    float o1 = (v1 - mu) * r;
    if (GATE) {
        o0 *= u[(size_t)row * MMW + t];
        o1 *= u[(size_t)row * MMW + t + 256];
    }
    outp[(size_t)row * DDIM + t]       = o0;
    outp[(size_t)row * DDIM + t + 256] = o1;
}

// ---------------------------------------------------------------------------
// TF32 tensor-core GEMM, 128x128x32 tile, 256 threads, warp tile 64x32.
// EPI==0: C = silu(A @ B),            B row-major [K x Nn]
// EPI==1: C = A @ B^T + bias + res,   B row-major [Nn x K]
// Smem layouts are fragment-shuffled:
//   Asf[msub(8)][kstep(4)][lane(32)][reg(4)]  (m16n8k8 A frags)
//   Bsf[nsub(16)][kstep(4)][lane(32)][reg(2)] (m16n8k8 B frags)
// ---------------------------------------------------------------------------
template<int EPI>
__global__ __launch_bounds__(256) void tgemm_kernel(
    const float* __restrict__ A, const float* __restrict__ Bm,
    const float* __restrict__ bias, const float* __restrict__ res,
    float* __restrict__ C, int M, int Nn, int K)
{
    __shared__ __align__(16) uint32_t Asf[4096];
    __shared__ __align__(16) uint32_t Bsf[4096];
    const int tid  = threadIdx.x;
    const int lane = tid & 31;
    const int w    = tid >> 5;
    const int wm   = w >> 2, wn = w & 3;
    const int g    = lane >> 2, tig = lane & 3;
    const int n0 = blockIdx.x * 128;
    const int m0 = blockIdx.y * 128;
    float acc[4][4][4] = {};

    for (int k0 = 0; k0 < K; k0 += 32) {
        __syncthreads();
        // --- A tile: rows m0..+127, cols k0..+31, scatter to frag layout ---
        #pragma unroll
        for (int ii = 0; ii < 4; ii++) {
            int f  = tid + ii * 256;           // 0..1023 float4s
            int r  = f >> 3;
            int cq = (f & 7) * 4;
            float4 a4 = *(const float4*)(A + (size_t)(m0 + r) * K + k0 + cq);
            float av[4] = {a4.x, a4.y, a4.z, a4.w};
            int msub = r >> 4, mrr = r & 15, gg = mrr & 7, hi = mrr >> 3;
            #pragma unroll
            for (int e = 0; e < 4; e++) {
                int kc = cq + e, ks = kc >> 3, kk = kc & 7;
                Asf[((msub * 4 + ks) * 32 + gg * 4 + (kk & 3)) * 4 + hi + 2 * (kk >> 2)] = f2tf(av[e]);
            }
        }
        // --- B tile ---
        if (EPI == 0) {
            #pragma unroll
            for (int ii = 0; ii < 4; ii++) {
                int f  = tid + ii * 256;
                int r  = f >> 5;                 // k row 0..31
                int cq = (f & 31) * 4;           // n col
                float4 b4 = *(const float4*)(Bm + (size_t)(k0 + r) * Nn + n0 + cq);
                float bv[4] = {b4.x, b4.y, b4.z, b4.w};
                int ks = r >> 3, kk = r & 7;
                #pragma unroll
                for (int e = 0; e < 4; e++) {
                    int nc = cq + e;
                    Bsf[(((nc >> 3) * 4 + ks) * 32 + (nc & 7) * 4 + (kk & 3)) * 2 + (kk >> 2)] = f2tf(bv[e]);
                }
            }
        } else {
            #pragma unroll
            for (int ii = 0; ii < 4; ii++) {
                int f  = tid + ii * 256;
                int nn = f >> 3;                 // n (row of Bm)
                int kq = (f & 7) * 4;            // k
                float4 b4 = *(const float4*)(Bm + (size_t)(n0 + nn) * K + k0 + kq);
                float bv[4] = {b4.x, b4.y, b4.z, b4.w};
                #pragma unroll
                for (int e = 0; e < 4; e++) {
                    int kc = kq + e, ks = kc >> 3, kk = kc & 7;
                    Bsf[(((nn >> 3) * 4 + ks) * 32 + (nn & 7) * 4 + (kk & 3)) * 2 + (kk >> 2)] = f2tf(bv[e]);
                }
            }
        }
        __syncthreads();
        // --- compute ---
        #pragma unroll
        for (int ks = 0; ks < 4; ks++) {
            uint4 af[4]; uint2 bf[4];
            #pragma unroll
            for (int i = 0; i < 4; i++)
                af[i] = *(const uint4*)&Asf[(((wm * 4 + i) * 4 + ks) * 32 + lane) * 4];
            #pragma unroll
            for (int j = 0; j < 4; j++)
                bf[j] = *(const uint2*)&Bsf[(((wn * 4 + j) * 4 + ks) * 32 + lane) * 2];
            #pragma unroll
            for (int i = 0; i < 4; i++)
                #pragma unroll
                for (int j = 0; j < 4; j++)
                    mma8(acc[i][j], (const uint32_t*)&af[i], (const uint32_t*)&bf[j]);
        }
    }

    // --- epilogue ---
    #pragma unroll
    for (int i = 0; i < 4; i++) {
        #pragma unroll
        for (int j = 0; j < 4; j++) {
            int gm = m0 + wm * 64 + i * 16 + g;
            int gn = n0 + wn * 32 + j * 8 + tig * 2;
            float2 lo, hi2;
            lo.x  = acc[i][j][0]; lo.y  = acc[i][j][1];
            hi2.x = acc[i][j][2]; hi2.y = acc[i][j][3];
            if (EPI == 0) {
                lo.x = silu_f(lo.x);  lo.y = silu_f(lo.y);
                hi2.x = silu_f(hi2.x); hi2.y = silu_f(hi2.y);
            } else {
                float2 b2 = *(const float2*)(bias + gn);
                float2 r0 = *(const float2*)(res + (size_t)gm * Nn + gn);
                float2 r1 = *(const float2*)(res + (size_t)(gm + 8) * Nn + gn);
                lo.x += b2.x + r0.x;  lo.y += b2.y + r0.y;
                hi2.x += b2.x + r1.x; hi2.y += b2.y + r1.y;
            }
            *(float2*)(C + (size_t)gm * Nn + gn)       = lo;
            *(float2*)(C + (size_t)(gm + 8) * Nn + gn) = hi2;
        }
    }
}

// ---------------------------------------------------------------------------
// Fused causal silu-attention on tensor cores.
//   O[n,:] = sum_{m<=n} (silu(q_n.k_m)/N) * v_m     per (b,h)
// Q tile 128 rows, KV tile 128. QK^T via tf32 mma; silu in C frags; C-frags
// shuffled in-register into A frags for S@V mma (no S smem).
// Smem (dynamic 96KB): Qsf[8][8][32][4], Ksf[16][8][32][2], Vsf[8][16][32][2]
// ---------------------------------------------------------------------------
__global__ __launch_bounds__(256) void attn_kernel(const float* __restrict__ mm,
                                                   float* __restrict__ attn_out)
{
    extern __shared__ __align__(16) uint32_t smeman[];
    uint32_t* Qsf = smeman;          // 8192 u32
    uint32_t* Ksf = Qsf + 8192;      // 8192 u32
    uint32_t* Vsf = Ksf + 8192;      // 8192 u32
    float*    Obuf = (float*)Ksf;    // reused after main loop: [2][64][68]

    const int tid  = threadIdx.x;
    const int lane = tid & 31;
    const int w    = tid >> 5;
    const int wm   = w >> 2, wn = w & 3;
    const int g    = lane >> 2, tig = lane & 3;
    const unsigned FULL = 0xffffffffu;

    const int nt = (int)gridDim.x - 1 - (int)blockIdx.x;  // heavy tiles first
    const int bh = blockIdx.y;
    const int b  = bh >> 3, h = bh & 7;
    const size_t rowbase = (size_t)b * NNQ;
    const float* qbase = mm + rowbase * MMW + 1024 + h * 64;
    const float* kbase = mm + rowbase * MMW + 1536 + h * 64;
    const float* vbase = mm + rowbase * MMW + 512  + h * 64;
    const int n0 = nt * 128;
    const float inv_n = 1.0f / (float)NNQ;

    // Load Q tile -> A-frag layout
    #pragma unroll
    for (int ii = 0; ii < 8; ii++) {
        int f  = tid + ii * 256;          // 0..2047 float4s
        int r  = f >> 4;
        int cq = (f & 15) * 4;
        float4 q4 = *(const float4*)(qbase + (size_t)(n0 + r) * MMW + cq);
        float qv[4] = {q4.x, q4.y, q4.z, q4.w};
        int msub = r >> 4, mrr = r & 15, gg = mrr & 7, hi = mrr >> 3;
        #pragma unroll
        for (int e = 0; e < 4; e++) {
            int c = cq + e, ks = c >> 3, kk = c & 7;
            Qsf[((msub * 8 + ks) * 32 + gg * 4 + (kk & 3)) * 4 + hi + 2 * (kk >> 2)] = f2tf(qv[e]);
        }
    }

    float o_part[4][8][4] = {};   // warp-local O partial: rows wm*64.., all 64 dl cols

    for (int mt = 0; mt <= nt; mt++) {
        const int m0 = mt * 128;
        const bool diag = (mt == nt);
        __syncthreads();   // prior iter done with Ksf/Vsf (and Q visible on iter 0)

        // Load K (B-frag layout, n=kv row, k=d) and V (B-frag, n=dl, k=kv row)
        #pragma unroll
        for (int ii = 0; ii < 8; ii++) {
            int f  = tid + ii * 256;
            int r  = f >> 4;
            int cq = (f & 15) * 4;
            float4 k4 = *(const float4*)(kbase + (size_t)(m0 + r) * MMW + cq);
            float4 v4 = *(const float4*)(vbase + (size_t)(m0 + r) * MMW + cq);
            float kv[4] = {k4.x, k4.y, k4.z, k4.w};
            float vv[4] = {v4.x, v4.y, v4.z, v4.w};
            int knsub = r >> 3, kg = r & 7;        // K: n = r
            int vks = r >> 3, vkk = r & 7;         // V: k = r
            #pragma unroll
            for (int e = 0; e < 4; e++) {
                int c = cq + e;
                int ks = c >> 3, kk = c & 7;       // K: k = c
                Ksf[((knsub * 8 + ks) * 32 + kg * 4 + (kk & 3)) * 2 + (kk >> 2)] = f2tf(kv[e]);
                Vsf[(((c >> 3) * 16 + vks) * 32 + (c & 7) * 4 + (vkk & 3)) * 2 + (vkk >> 2)] = f2tf(vv[e]);
            }
        }
        __syncthreads();

        // S = Q K^T : warp tile 64(m) x 32(kv)
        float s_acc[4][4][4] = {};
        #pragma unroll
        for (int ks = 0; ks < 8; ks++) {
            uint4 af[4]; uint2 bf[4];
            #pragma unroll
            for (int i = 0; i < 4; i++)
                af[i] = *(const uint4*)&Qsf[(((wm * 4 + i) * 8 + ks) * 32 + lane) * 4];
            #pragma unroll
            for (int j = 0; j < 4; j++)
                bf[j] = *(const uint2*)&Ksf[(((wn * 4 + j) * 8 + ks) * 32 + lane) * 2];
            #pragma unroll
            for (int i = 0; i < 4; i++)
                #pragma unroll
                for (int j = 0; j < 4; j++)
                    mma8(s_acc[i][j], (const uint32_t*)&af[i], (const uint32_t*)&bf[j]);
        }

        // silu/mask -> shuffle C-frags into A-frags -> S @ V accumulation
        #pragma unroll
        for (int j = 0; j < 4; j++) {
            const int kstep = wn * 4 + j;    // kv 8-block index for AV
            uint2 vb[8];
            #pragma unroll
            for (int ns = 0; ns < 8; ns++)
                vb[ns] = *(const uint2*)&Vsf[((ns * 16 + kstep) * 32 + lane) * 2];
            #pragma unroll
            for (int i = 0; i < 4; i++) {
                float e0, e1, e2, e3;
                {
                    float v0 = s_acc[i][j][0], v1 = s_acc[i][j][1];
                    float v2 = s_acc[i][j][2], v3 = s_acc[i][j][3];
                    e0 = silu_f(v0) * inv_n; e1 = silu_f(v1) * inv_n;
                    e2 = silu_f(v2) * inv_n; e3 = silu_f(v3) * inv_n;
                    if (diag) {
                        int rlo = wm * 64 + i * 16 + g;
                        int rhi = rlo + 8;
                        int c0 = wn * 32 + j * 8 + tig * 2;
                        int c1 = c0 + 1;
                        if (c0 > rlo) e0 = 0.f;
                        if (c1 > rlo) e1 = 0.f;
                        if (c0 > rhi) e2 = 0.f;
                        if (c1 > rhi) e3 = 0.f;
                    }
                }
                int src0 = (lane & 0x1c) | (tig >> 1);
                int src2 = src0 + 2;
                float x0, x1;
                uint32_t a[4];
                x0 = __shfl_sync(FULL, e0, src0); x1 = __shfl_sync(FULL, e1, src0);
                a[0] = f2tf((tig & 1) ? x1 : x0);
                x0 = __shfl_sync(FULL, e2, src0); x1 = __shfl_sync(FULL, e3, src0);
                a[1] = f2tf((tig & 1) ? x1 : x0);
                x0 = __shfl_sync(FULL, e0, src2); x1 = __shfl_sync(FULL, e1, src2);
                a[2] = f2tf((tig & 1) ? x1 : x0);
                x0 = __shfl_sync(FULL, e2, src2); x1 = __shfl_sync(FULL, e3, src2);
                a[3] = f2tf((tig & 1) ? x1 : x0);
                #pragma unroll
                for (int ns = 0; ns < 8; ns++)
                    mma8(o_part[i][ns], a, (const uint32_t*)&vb[ns]);
            }
        }
    }

    // Cross-warp reduction over wn (4 warps share rows wm*64..+63)
    __syncthreads();
    #define OB(wmi, r_, c_) Obuf[(wmi) * 4352 + (r_) * 68 + (c_)]
    if (wn == 0) {
        #pragma unroll
        for (int i = 0; i < 4; i++)
            #pragma unroll
            for (int ns = 0; ns < 8; ns++) {
                int r = i * 16 + g, c = ns * 8 + tig * 2;
                *(float2*)&OB(wm, r, c)     = make_float2(o_part[i][ns][0], o_part[i][ns][1]);
                *(float2*)&OB(wm, r + 8, c) = make_float2(o_part[i][ns][2], o_part[i][ns][3]);
            }
    }
    __syncthreads();
    for (int rr = 1; rr < 4; rr++) {
        if (wn == rr) {
            #pragma unroll
            for (int i = 0; i < 4; i++)
                #pragma unroll
                for (int ns = 0; ns < 8; ns++) {
                    int r = i * 16 + g, c = ns * 8 + tig * 2;
                    float2 p0 = *(float2*)&OB(wm, r, c);
                    p0.x += o_part[i][ns][0]; p0.y += o_part[i][ns][1];
                    *(float2*)&OB(wm, r, c) = p0;
                    float2 p1 = *(float2*)&OB(wm, r + 8, c);
                    p1.x += o_part[i][ns][2]; p1.y += o_part[i][ns][3];
                    *(float2*)&OB(wm, r + 8, c) = p1;
                }
        }
        __syncthreads();
    }

    // Write 128 x 64 tile to global
    #pragma unroll
    for (int ii = 0; ii < 16; ii++) {
        int f   = tid + ii * 256;        // 0..4095 float2s
        int row = f >> 5;
        int cp  = (f & 31) * 2;
        float2 v = *(float2*)&OB(row >> 6, row & 63, cp);
        *(float2*)&attn_out[(rowbase + n0 + row) * DDIM + h * 64 + cp] = v;
    }
    #undef OB
}

// ---------------------------------------------------------------------------
extern "C" void kernel_launch(void* const* d_in, const int* in_sizes, int n_in,
                              void* d_out, int out_size)
{
    const float* x = nullptr; const float* uvqk = nullptr;
    const float* o_w = nullptr; const float* o_b = nullptr;
    for (int i = 0; i < n_in; i++) {
        int sz = in_sizes[i];
        if      (sz == ROWS * DDIM)  x    = (const float*)d_in[i];
        else if (sz == DDIM * MMW)   uvqk = (const float*)d_in[i];
        else if (sz == DDIM * DDIM)  o_w  = (const float*)d_in[i];
        else if (sz == DDIM)         o_b  = (const float*)d_in[i];
        // attention_mask is the fixed causal tril; handled analytically
    }
    float* outp = (float*)d_out;

    float *p_xn, *p_mm, *p_attn, *p_oin;
    cudaGetSymbolAddress((void**)&p_xn,   g_xn);
    cudaGetSymbolAddress((void**)&p_mm,   g_mm);
    cudaGetSymbolAddress((void**)&p_attn, g_attn);
    cudaGetSymbolAddress((void**)&p_oin,  g_oin);

    // 1) xn = LN(x)
    ln_kernel<false><<<ROWS, 256>>>(x, nullptr, p_xn);
    // 2) mm = silu(xn @ uvqk)
    tgemm_kernel<0><<<dim3(MMW / 128, ROWS / 128), 256>>>(
        p_xn, uvqk, nullptr, nullptr, p_mm, ROWS, MMW, DDIM);
    // 3) attn = causal silu-attention (96KB dynamic smem)
    cudaFuncSetAttribute(attn_kernel, cudaFuncAttributeMaxDynamicSharedMemorySize,
                         96 * 1024);
    attn_kernel<<<dim3(NNQ / 128, BB * HHH), 256, 96 * 1024>>>(p_mm, p_attn);
    // 4) oin = u * LN(attn)
    ln_kernel<true><<<ROWS, 256>>>(p_attn, p_mm, p_oin);
    // 5) out = oin @ o_w^T + o_b + x
    tgemm_kernel<1><<<dim3(DDIM / 128, ROWS / 128), 256>>>(
        p_oin, o_w, o_b, x, outp, ROWS, DDIM, DDIM);
}